// round 5
// baseline (speedup 1.0000x reference)
#include <cuda_runtime.h>
#include <math.h>

#define NN 50000
#define EE 400000
#define DMAX 256

// ---------------- scratch (static device globals; no allocation) ----------------
__device__ float g_h[(size_t)NN * DMAX];
__device__ float g_x[(size_t)NN * DMAX];
__device__ float g_y[(size_t)NN * DMAX];
__device__ float g_s[NN * 4];
__device__ float g_d[NN * 4];
__device__ int g_src[EE];
__device__ int g_dst[EE];
__device__ int g_ecol[EE];
__device__ int g_rowptr[NN + 1];
__device__ int g_deg[NN];
__device__ int g_cursor[NN];
__device__ int g_bsum[64];
__device__ int g_role[NN];
__device__ int g_is64;

// ---------------- helpers ----------------
__device__ __forceinline__ float warpSum(float v) {
    #pragma unroll
    for (int o = 16; o > 0; o >>= 1) v += __shfl_xor_sync(0xffffffffu, v, o);
    return v;
}
__device__ __forceinline__ int warpSumI(int v) {
    #pragma unroll
    for (int o = 16; o > 0; o >>= 1) v += __shfl_xor_sync(0xffffffffu, v, o);
    return v;
}
__device__ __forceinline__ int warpInclScan(int v, int lane) {
    #pragma unroll
    for (int o = 1; o < 32; o <<= 1) {
        int t = __shfl_up_sync(0xffffffffu, v, o);
        if (lane >= o) v += t;
    }
    return v;
}
__device__ __forceinline__ float leaky(float v) { return v > 0.f ? v : 0.2f * v; }

__device__ __forceinline__ unsigned f2tf32(float x) {
    unsigned r;
    asm("cvt.rna.tf32.f32 %0, %1;" : "=r"(r) : "f"(x));
    return r;
}

#define MMA_TF32(c, a, b)                                                        \
    asm volatile("mma.sync.aligned.m16n8k8.row.col.f32.tf32.tf32.f32 "           \
                 "{%0,%1,%2,%3}, {%4,%5,%6,%7}, {%8,%9}, {%0,%1,%2,%3};"         \
                 : "+f"((c)[0]), "+f"((c)[1]), "+f"((c)[2]), "+f"((c)[3])        \
                 : "r"((a)[0]), "r"((a)[1]), "r"((a)[2]), "r"((a)[3]),           \
                   "r"((b)[0]), "r"((b)[1]))

// ---------------- dtype detect + prep ----------------
__global__ void detect_kernel(const unsigned int* __restrict__ w, int* flag) {
    if (threadIdx.x == 0 && blockIdx.x == 0) {
        int is64 = 1;
        for (int i = 0; i < 64; i++)
            if (w[2 * i + 1] != 0u) { is64 = 0; break; }
        *flag = is64;
    }
}

__global__ void prep_kernel(const void* __restrict__ ei, const void* __restrict__ rid,
                            int* __restrict__ src, int* __restrict__ dst,
                            int* __restrict__ deg, int* __restrict__ role,
                            const int* __restrict__ flag, int E, int n) {
    int i = blockIdx.x * blockDim.x + threadIdx.x;
    int is64 = *flag;
    if (i < E) {
        int s, d;
        if (is64) {
            const long long* p = (const long long*)ei;
            s = (int)p[i];
            d = (int)p[(size_t)E + i];
        } else {
            const int* p = (const int*)ei;
            s = p[i];
            d = p[E + i];
        }
        src[i] = s;
        dst[i] = d;
        atomicAdd(&deg[d], 1);
    }
    if (i < n) {
        if (is64) role[i] = (int)((const long long*)rid)[i];
        else      role[i] = ((const int*)rid)[i];
    }
}

// ---------------- parallel 3-phase scan ----------------
__global__ void scan_reduce_kernel(const int* __restrict__ deg, int* __restrict__ bsum, int n) {
    __shared__ int sw[32];
    int tid = threadIdx.x, lane = tid & 31, w = tid >> 5;
    int i = blockIdx.x * 1024 + tid;
    int v = (i < n) ? deg[i] : 0;
    v = warpSumI(v);
    if (lane == 0) sw[w] = v;
    __syncthreads();
    if (w == 0) {
        int t = sw[lane];
        t = warpSumI(t);
        if (lane == 0) bsum[blockIdx.x] = t;
    }
}

__global__ void scan_bsum_kernel(int* __restrict__ bsum, int nb) {
    __shared__ int sh[64];
    int tid = threadIdx.x, lane = tid & 31, w = tid >> 5;
    int v = (tid < nb) ? bsum[tid] : 0;
    int iv = warpInclScan(v, lane);
    __shared__ int wtot[2];
    if (lane == 31) wtot[w] = iv;
    __syncthreads();
    int offs = (w == 1) ? wtot[0] : 0;
    sh[tid] = iv + offs - v;
    __syncthreads();
    if (tid < nb) bsum[tid] = sh[tid];
}

__global__ void scan_final_kernel(const int* __restrict__ deg, const int* __restrict__ bsum,
                                  int* __restrict__ rowptr, int* __restrict__ cursor, int n) {
    __shared__ int sw[32];
    int tid = threadIdx.x, lane = tid & 31, w = tid >> 5;
    int i = blockIdx.x * 1024 + tid;
    int v = (i < n) ? deg[i] : 0;
    int iv = warpInclScan(v, lane);
    if (lane == 31) sw[w] = iv;
    __syncthreads();
    if (w == 0) {
        int t = sw[lane];
        t = warpInclScan(t, lane);
        sw[lane] = t;
    }
    __syncthreads();
    int offs = ((w > 0) ? sw[w - 1] : 0) + bsum[blockIdx.x];
    int incl = iv + offs;
    if (i < n) {
        rowptr[i + 1] = incl;
        cursor[i] = incl - v;
    }
    if (i == 0) rowptr[0] = 0;
}

__global__ void scatter_kernel(const int* __restrict__ src, const int* __restrict__ dst,
                               int* __restrict__ cursor, int* __restrict__ ecol, int E) {
    int i = blockIdx.x * blockDim.x + threadIdx.x;
    if (i >= E) return;
    int pos = atomicAdd(&cursor[dst[i]], 1);
    ecol[pos] = src[i];
}

// ---------------- 3xTF32 tensor-core GEMM with fragment-permuted smem -----------------
// C[M,Nc] = A[M,K] * B[Nc,K]^T. block 128x64, k-chunk 32; 8 warps: 4(M) x 2(N),
// warp tile 32x32 (2x4 m16n8k8 frags). Fused attention-score epilogue (col block==head).
// smem (dynamic, 48KB): Ahi[4096] Alo[4096] Bhi[2048] Blo[2048] floats, fragment layout:
//   A: ((mt*4+kg)*32 + lane)*4 + slot, lane=r*4+c, slot=mhalf+2*khalf  -> LDS.128/frag
//   B: ((nt*4+kg)*32 + lane)*2 + slot, lane=n*4+c, slot=khalf          -> LDS.64/frag
#define TBM 128
#define TBN 64
#define TBK 32
#define GEMM_SMEM 49152

__global__ void __launch_bounds__(256) gemm_tf32(
        const float* __restrict__ A, const float* __restrict__ B,
        float* __restrict__ C, int M, int Nc, int K,
        const float* __restrict__ as_, const float* __restrict__ ad_,
        float* __restrict__ s_, float* __restrict__ d_, int H) {
    extern __shared__ float smem[];
    float* Ahi = smem;
    float* Alo = Ahi + 4096;
    float* Bhi = Alo + 4096;
    float* Blo = Bhi + 2048;

    int tid = threadIdx.x;
    int lane = tid & 31, warp = tid >> 5;
    int wm = warp & 3, wn = warp >> 2;
    int brow = blockIdx.y * TBM, bcol = blockIdx.x * TBN;

    float c[2][4][4];
    #pragma unroll
    for (int mi = 0; mi < 2; mi++)
        #pragma unroll
        for (int ni = 0; ni < 4; ni++)
            #pragma unroll
            for (int r = 0; r < 4; r++) c[mi][ni][r] = 0.f;

    // A-load geometry: 2 threads per row, 16 k each (4 float4)
    int arow = tid >> 1;
    int akbase = (tid & 1) * 16;
    int agm = brow + arow;
    // B-load geometry: 4 threads per row, 8 k each (2 float4)
    int nrow = tid >> 2;
    int bkbase = (tid & 3) * 8;

    for (int k0 = 0; k0 < K; k0 += TBK) {
        #pragma unroll
        for (int j = 0; j < 4; j++) {
            int k = akbase + j * 4;
            float4 v = make_float4(0.f, 0.f, 0.f, 0.f);
            if (agm < M) v = *(const float4*)&A[(size_t)agm * K + k0 + k];
            int mt = arow >> 4, rr = arow & 15, mh = rr >> 3, r = rr & 7;
            int kg = k >> 3, kh = (k & 7) >> 2;
            int base = ((mt * 4 + kg) * 32) * 4 + r * 16 + (mh + 2 * kh);
            float e[4] = {v.x, v.y, v.z, v.w};
            #pragma unroll
            for (int q = 0; q < 4; q++) {
                unsigned hi = f2tf32(e[q]);
                int addr = base + q * 4;
                Ahi[addr] = __uint_as_float(hi);
                Alo[addr] = __uint_as_float(f2tf32(e[q] - __uint_as_float(hi)));
            }
        }
        #pragma unroll
        for (int j = 0; j < 2; j++) {
            int k = bkbase + j * 4;
            int gn = bcol + nrow;
            float4 v = make_float4(0.f, 0.f, 0.f, 0.f);
            if (gn < Nc) v = *(const float4*)&B[(size_t)gn * K + k0 + k];
            int nt = nrow >> 3, nn = nrow & 7;
            int kg = k >> 3, kh = (k & 7) >> 2;
            int base = ((nt * 4 + kg) * 32) * 2 + nn * 8 + kh;
            float e[4] = {v.x, v.y, v.z, v.w};
            #pragma unroll
            for (int q = 0; q < 4; q++) {
                unsigned hi = f2tf32(e[q]);
                int addr = base + q * 2;
                Bhi[addr] = __uint_as_float(hi);
                Blo[addr] = __uint_as_float(f2tf32(e[q] - __uint_as_float(hi)));
            }
        }
        __syncthreads();

        #pragma unroll
        for (int kg = 0; kg < 4; kg++) {
            unsigned ah[2][4], al[2][4], bh[4][2], bl[4][2];
            #pragma unroll
            for (int mi = 0; mi < 2; mi++) {
                int mt = wm * 2 + mi;
                int idx = ((mt * 4 + kg) * 32 + lane) * 4;
                float4 vh = *(float4*)&Ahi[idx];
                float4 vl = *(float4*)&Alo[idx];
                ah[mi][0] = __float_as_uint(vh.x); ah[mi][1] = __float_as_uint(vh.y);
                ah[mi][2] = __float_as_uint(vh.z); ah[mi][3] = __float_as_uint(vh.w);
                al[mi][0] = __float_as_uint(vl.x); al[mi][1] = __float_as_uint(vl.y);
                al[mi][2] = __float_as_uint(vl.z); al[mi][3] = __float_as_uint(vl.w);
            }
            #pragma unroll
            for (int ni = 0; ni < 4; ni++) {
                int nt = wn * 4 + ni;
                int idx = ((nt * 4 + kg) * 32 + lane) * 2;
                float2 vh = *(float2*)&Bhi[idx];
                float2 vl = *(float2*)&Blo[idx];
                bh[ni][0] = __float_as_uint(vh.x); bh[ni][1] = __float_as_uint(vh.y);
                bl[ni][0] = __float_as_uint(vl.x); bl[ni][1] = __float_as_uint(vl.y);
            }
            #pragma unroll
            for (int mi = 0; mi < 2; mi++)
                #pragma unroll
                for (int ni = 0; ni < 4; ni++) {
                    MMA_TF32(c[mi][ni], ah[mi], bh[ni]);
                    MMA_TF32(c[mi][ni], ah[mi], bl[ni]);
                    MMA_TF32(c[mi][ni], al[mi], bh[ni]);
                }
        }
        __syncthreads();
    }

    // store C (fragment layout: rows r=lane>>2 (+8), cols (lane&3)*2 (+1))
    #pragma unroll
    for (int mi = 0; mi < 2; mi++) {
        #pragma unroll
        for (int ni = 0; ni < 4; ni++) {
            int m = brow + wm * 32 + mi * 16 + (lane >> 2);
            int n = bcol + wn * 32 + ni * 8 + ((lane & 3) << 1);
            if (m < M)
                *(float2*)&C[(size_t)m * Nc + n] = make_float2(c[mi][ni][0], c[mi][ni][1]);
            if (m + 8 < M)
                *(float2*)&C[(size_t)(m + 8) * Nc + n] = make_float2(c[mi][ni][2], c[mi][ni][3]);
        }
    }

    // fused score epilogue: this column block is one head
    int head = blockIdx.x;
    float* s_red = smem;           // 128
    float* d_red = smem + 128;     // 128
    if (tid < 256) smem[tid] = 0.f;
    __syncthreads();
    #pragma unroll
    for (int mi = 0; mi < 2; mi++) {
        #pragma unroll
        for (int part = 0; part < 2; part++) {
            int m_loc = wm * 32 + mi * 16 + (lane >> 2) + part * 8;
            float ss = 0.f, dd = 0.f;
            #pragma unroll
            for (int ni = 0; ni < 4; ni++) {
                int n0 = wn * 32 + ni * 8 + ((lane & 3) << 1);
                float a0 = as_[head * 64 + n0], a1 = as_[head * 64 + n0 + 1];
                float e0 = ad_[head * 64 + n0], e1 = ad_[head * 64 + n0 + 1];
                float c0 = c[mi][ni][part * 2], c1 = c[mi][ni][part * 2 + 1];
                ss += c0 * a0 + c1 * a1;
                dd += c0 * e0 + c1 * e1;
            }
            ss += __shfl_xor_sync(0xffffffffu, ss, 1);
            ss += __shfl_xor_sync(0xffffffffu, ss, 2);
            dd += __shfl_xor_sync(0xffffffffu, dd, 1);
            dd += __shfl_xor_sync(0xffffffffu, dd, 2);
            if ((lane & 3) == 0) {
                atomicAdd(&s_red[m_loc], ss);
                atomicAdd(&d_red[m_loc], dd);
            }
        }
    }
    __syncthreads();
    if (tid < 128) {
        int gm = brow + tid;
        if (gm < M) {
            s_[(size_t)gm * H + head] = s_red[tid];
            d_[(size_t)gm * H + head] = d_red[tid];
        }
    }
}

// ---------------- fused per-dst: softmax + aggregate + bias/ELU + LayerNorm ------------
template<int H>
__global__ void gat_fused(const int* __restrict__ rowptr, const int* __restrict__ ecol,
                          const float* __restrict__ s_, const float* __restrict__ d_,
                          const float* __restrict__ h, const float* __restrict__ bias,
                          const float* __restrict__ lw, const float* __restrict__ lb,
                          float* __restrict__ outp, int n, int do_elu) {
    const int D = H * 64;
    const int NV = D / 32;
    int warp = (blockIdx.x * blockDim.x + threadIdx.x) >> 5;
    int lane = threadIdx.x & 31;
    if (warp >= n) return;
    int node = warp;
    int start = rowptr[node], end = rowptr[node + 1];

    float dsel[H], selfv[H];
    #pragma unroll
    for (int q = 0; q < H; q++) {
        float sv = s_[(size_t)node * H + q];
        float dv = d_[(size_t)node * H + q];
        dsel[q] = dv;
        selfv[q] = leaky(sv + dv);
    }
    float mx[H];
    #pragma unroll
    for (int q = 0; q < H; q++) mx[q] = selfv[q];
    for (int e = start + lane; e < end; e += 32) {
        int src = ecol[e];
        #pragma unroll
        for (int q = 0; q < H; q++) {
            float v = leaky(s_[(size_t)src * H + q] + dsel[q]);
            mx[q] = fmaxf(mx[q], v);
        }
    }
    #pragma unroll
    for (int q = 0; q < H; q++)
        #pragma unroll
        for (int o = 16; o > 0; o >>= 1) mx[q] = fmaxf(mx[q], __shfl_xor_sync(0xffffffffu, mx[q], o));

    float sm[H];
    #pragma unroll
    for (int q = 0; q < H; q++) sm[q] = 0.f;
    for (int e = start + lane; e < end; e += 32) {
        int src = ecol[e];
        #pragma unroll
        for (int q = 0; q < H; q++) {
            float v = leaky(s_[(size_t)src * H + q] + dsel[q]);
            sm[q] += expf(v - mx[q]);
        }
    }
    float inv[H], aself[H];
    #pragma unroll
    for (int q = 0; q < H; q++) {
        float tot = warpSum(sm[q]) + expf(selfv[q] - mx[q]);
        inv[q] = 1.f / (tot + 1e-16f);
        aself[q] = expf(selfv[q] - mx[q]) * inv[q];
    }

    int hl = lane & 3;
    float d_hl, m_hl, i_hl;
    if (H == 4) {
        d_hl = (hl == 0) ? dsel[0] : (hl == 1) ? dsel[1] : (hl == 2) ? dsel[2] : dsel[3];
        m_hl = (hl == 0) ? mx[0]   : (hl == 1) ? mx[1]   : (hl == 2) ? mx[2]   : mx[3];
        i_hl = (hl == 0) ? inv[0]  : (hl == 1) ? inv[1]  : (hl == 2) ? inv[2]  : inv[3];
    } else {
        d_hl = dsel[0]; m_hl = mx[0]; i_hl = inv[0];
    }

    float accv[NV];
    const float* hps = h + (size_t)node * D;
    #pragma unroll
    for (int i = 0; i < NV; i++) accv[i] = hps[lane + i * 32] * aself[i >> 1];

    for (int e0 = start; e0 < end; e0 += 8) {
        int me = e0 + (lane >> 2);
        float alpha = 0.f;
        int msrc = 0;
        if (me < end && hl < H) {
            msrc = ecol[me];
            float v = leaky(s_[(size_t)msrc * H + hl] + d_hl);
            alpha = expf(v - m_hl) * i_hl;
        }
        int cnt = end - e0; if (cnt > 8) cnt = 8;
        for (int j = 0; j < cnt; j++) {
            int src = __shfl_sync(0xffffffffu, msrc, j * 4);
            const float* hp = h + (size_t)src * D;
            #pragma unroll
            for (int i = 0; i < NV; i++) {
                float al = __shfl_sync(0xffffffffu, alpha, j * 4 + (i >> 1));
                accv[i] += hp[lane + i * 32] * al;
            }
        }
    }

    float ssum = 0.f;
    #pragma unroll
    for (int i = 0; i < NV; i++) {
        int cidx = lane + i * 32;
        float v = accv[i] + bias[cidx];
        if (do_elu) v = v > 0.f ? v : (expf(v) - 1.f);
        accv[i] = v;
        ssum += v;
    }
    ssum = warpSum(ssum);
    float mu = ssum / (float)D;
    float vs = 0.f;
    #pragma unroll
    for (int i = 0; i < NV; i++) { float t = accv[i] - mu; vs += t * t; }
    vs = warpSum(vs);
    float rs = rsqrtf(vs / (float)D + 1e-5f);
    float* orow = outp + (size_t)node * D;
    #pragma unroll
    for (int i = 0; i < NV; i++) {
        int cidx = lane + i * 32;
        orow[cidx] = (accv[i] - mu) * rs * lw[cidx] + lb[cidx];
    }
}

// ---------------- final MLP head ----------------
__global__ void head_kernel(const float* __restrict__ h3, const int* __restrict__ role,
                            const float* __restrict__ rt, const float* __restrict__ p1w,
                            const float* __restrict__ p1b, const float* __restrict__ p2w,
                            const float* __restrict__ p2b, float* __restrict__ z, int n) {
    extern __shared__ float sm[];
    float* sp1 = sm;
    float* sp2 = sp1 + 128 * 64;
    float* sz  = sp2 + 64 * 64;
    float* sz1 = sz + 4 * 128;
    int tid = threadIdx.x;
    for (int i = tid; i < 128 * 64; i += 256) {
        int j = i / 128, k = i % 128;
        sp1[k * 64 + j] = p1w[i];
    }
    for (int i = tid; i < 64 * 64; i += 256) {
        int j = i / 64, k = i % 64;
        sp2[k * 64 + j] = p2w[i];
    }
    __syncthreads();
    int g = tid >> 6, j = tid & 63;
    float b1v = p1b[j], b2v = p2b[j];
    for (int it = 0; it < 16; it++) {
        int node = blockIdx.x * 64 + it * 4 + g;
        bool valid = node < n;
        if (valid) {
            sz[g * 128 + j] = h3[(size_t)node * 64 + j];
            int r = role[node];
            sz[g * 128 + 64 + j] = rt[r * 64 + j];
        }
        __syncthreads();
        float acc = b1v;
        #pragma unroll 8
        for (int k = 0; k < 128; k++) acc += sp1[k * 64 + j] * sz[g * 128 + k];
        sz1[g * 64 + j] = fmaxf(acc, 0.f);
        __syncthreads();
        float acc2 = b2v;
        #pragma unroll 8
        for (int k = 0; k < 64; k++) acc2 += sp2[k * 64 + j] * sz1[g * 64 + k];
        if (valid) z[(size_t)node * 64 + j] = acc2;
    }
}

// ---------------- host orchestration ----------------
extern "C" void kernel_launch(void* const* d_in, const int* in_sizes, int n_in,
                              void* d_out, int out_size) {
    const float* x   = (const float*)d_in[0];
    const void*  ei  = d_in[1];
    const void*  rid = d_in[2];
    const float* W1  = (const float*)d_in[3];
    const float* a1s = (const float*)d_in[4];
    const float* a1d = (const float*)d_in[5];
    const float* b1  = (const float*)d_in[6];
    const float* W2  = (const float*)d_in[7];
    const float* a2s = (const float*)d_in[8];
    const float* a2d = (const float*)d_in[9];
    const float* b2  = (const float*)d_in[10];
    const float* W3  = (const float*)d_in[11];
    const float* a3s = (const float*)d_in[12];
    const float* a3d = (const float*)d_in[13];
    const float* b3  = (const float*)d_in[14];
    const float* ln1w = (const float*)d_in[15];
    const float* ln1b = (const float*)d_in[16];
    const float* ln2w = (const float*)d_in[17];
    const float* ln2b = (const float*)d_in[18];
    const float* ln3w = (const float*)d_in[19];
    const float* ln3b = (const float*)d_in[20];
    const float* rt   = (const float*)d_in[21];
    const float* p1w  = (const float*)d_in[22];
    const float* p1b  = (const float*)d_in[23];
    const float* p2w  = (const float*)d_in[24];
    const float* p2b  = (const float*)d_in[25];
    float* z = (float*)d_out;

    float *hbuf, *xbuf, *ybuf, *sp, *dp;
    int *srcp, *dstp, *ecolp, *rowp, *degp, *curp, *bsump, *rolep, *flagp;
    cudaGetSymbolAddress((void**)&hbuf, g_h);
    cudaGetSymbolAddress((void**)&xbuf, g_x);
    cudaGetSymbolAddress((void**)&ybuf, g_y);
    cudaGetSymbolAddress((void**)&sp, g_s);
    cudaGetSymbolAddress((void**)&dp, g_d);
    cudaGetSymbolAddress((void**)&srcp, g_src);
    cudaGetSymbolAddress((void**)&dstp, g_dst);
    cudaGetSymbolAddress((void**)&ecolp, g_ecol);
    cudaGetSymbolAddress((void**)&rowp, g_rowptr);
    cudaGetSymbolAddress((void**)&degp, g_deg);
    cudaGetSymbolAddress((void**)&curp, g_cursor);
    cudaGetSymbolAddress((void**)&bsump, g_bsum);
    cudaGetSymbolAddress((void**)&rolep, g_role);
    cudaGetSymbolAddress((void**)&flagp, g_is64);

    const int n = NN, E = EE;
    const int nb = (n + 1023) / 1024;

    cudaFuncSetAttribute(gemm_tf32, cudaFuncAttributeMaxDynamicSharedMemorySize, GEMM_SMEM);

    detect_kernel<<<1, 32>>>((const unsigned int*)ei, flagp);
    cudaMemsetAsync(degp, 0, n * sizeof(int));
    prep_kernel<<<(E + 255) / 256, 256>>>(ei, rid, srcp, dstp, degp, rolep, flagp, E, n);
    scan_reduce_kernel<<<nb, 1024>>>(degp, bsump, n);
    scan_bsum_kernel<<<1, 64>>>(bsump, nb);
    scan_final_kernel<<<nb, 1024>>>(degp, bsump, rowp, curp, n);
    scatter_kernel<<<(E + 255) / 256, 256>>>(srcp, dstp, curp, ecolp, E);

    dim3 g1(256 / TBN, (n + TBM - 1) / TBM);
    dim3 g3(64 / TBN, (n + TBM - 1) / TBM);
    int fusedBlocks = (n * 32 + 255) / 256;

    // layer 1: 64 -> 4x64 concat, elu + LN  (scores fused into GEMM epilogue)
    gemm_tf32<<<g1, 256, GEMM_SMEM>>>(x, W1, hbuf, n, 256, 64, a1s, a1d, sp, dp, 4);
    gat_fused<4><<<fusedBlocks, 256>>>(rowp, ecolp, sp, dp, hbuf, b1, ln1w, ln1b, xbuf, n, 1);

    // layer 2: 256 -> 4x64 concat, elu + LN
    gemm_tf32<<<g1, 256, GEMM_SMEM>>>(xbuf, W2, hbuf, n, 256, 256, a2s, a2d, sp, dp, 4);
    gat_fused<4><<<fusedBlocks, 256>>>(rowp, ecolp, sp, dp, hbuf, b2, ln2w, ln2b, xbuf, n, 1);

    // layer 3: 256 -> 1x64, LN only
    gemm_tf32<<<g3, 256, GEMM_SMEM>>>(xbuf, W3, hbuf, n, 64, 256, a3s, a3d, sp, dp, 1);
    gat_fused<1><<<fusedBlocks, 256>>>(rowp, ecolp, sp, dp, hbuf, b3, ln3w, ln3b, ybuf, n, 0);

    // final MLP head
    size_t smem = (128 * 64 + 64 * 64 + 4 * 128 + 4 * 64) * sizeof(float);
    cudaFuncSetAttribute(head_kernel, cudaFuncAttributeMaxDynamicSharedMemorySize, (int)smem);
    head_kernel<<<(n + 63) / 64, 256, smem>>>(ybuf, rolep, rt, p1w, p1b, p2w, p2b, z, n);
}

// round 6
// speedup vs baseline: 1.2279x; 1.2279x over previous
#include <cuda_runtime.h>
#include <math.h>

#define NN 50000
#define EE 400000
#define DMAX 256

// ---------------- scratch (static device globals; no allocation) ----------------
__device__ float g_h[(size_t)NN * DMAX];
__device__ float g_x[(size_t)NN * DMAX];
__device__ float g_y[(size_t)NN * DMAX];
__device__ float g_s[NN * 4];
__device__ float g_d[NN * 4];
__device__ int g_src[EE];
__device__ int g_dst[EE];
__device__ int g_ecol[EE];
__device__ int g_rowptr[NN + 1];
__device__ int g_deg[NN];
__device__ int g_cursor[NN];
__device__ int g_bsum[64];
__device__ int g_role[NN];
__device__ int g_is64;

// ---------------- helpers ----------------
__device__ __forceinline__ float warpSum(float v) {
    #pragma unroll
    for (int o = 16; o > 0; o >>= 1) v += __shfl_xor_sync(0xffffffffu, v, o);
    return v;
}
__device__ __forceinline__ int warpSumI(int v) {
    #pragma unroll
    for (int o = 16; o > 0; o >>= 1) v += __shfl_xor_sync(0xffffffffu, v, o);
    return v;
}
__device__ __forceinline__ int warpInclScan(int v, int lane) {
    #pragma unroll
    for (int o = 1; o < 32; o <<= 1) {
        int t = __shfl_up_sync(0xffffffffu, v, o);
        if (lane >= o) v += t;
    }
    return v;
}
__device__ __forceinline__ float leaky(float v) { return v > 0.f ? v : 0.2f * v; }

// ---------------- dtype detect + prep ----------------
__global__ void detect_kernel(const unsigned int* __restrict__ w, int* flag) {
    if (threadIdx.x == 0 && blockIdx.x == 0) {
        int is64 = 1;
        for (int i = 0; i < 64; i++)
            if (w[2 * i + 1] != 0u) { is64 = 0; break; }
        *flag = is64;
    }
}

__global__ void prep_kernel(const void* __restrict__ ei, const void* __restrict__ rid,
                            int* __restrict__ src, int* __restrict__ dst,
                            int* __restrict__ deg, int* __restrict__ role,
                            const int* __restrict__ flag, int E, int n) {
    int i = blockIdx.x * blockDim.x + threadIdx.x;
    int is64 = *flag;
    if (i < E) {
        int s, d;
        if (is64) {
            const long long* p = (const long long*)ei;
            s = (int)p[i];
            d = (int)p[(size_t)E + i];
        } else {
            const int* p = (const int*)ei;
            s = p[i];
            d = p[E + i];
        }
        src[i] = s;
        dst[i] = d;
        atomicAdd(&deg[d], 1);
    }
    if (i < n) {
        if (is64) role[i] = (int)((const long long*)rid)[i];
        else      role[i] = ((const int*)rid)[i];
    }
}

// ---------------- parallel 3-phase scan ----------------
__global__ void scan_reduce_kernel(const int* __restrict__ deg, int* __restrict__ bsum, int n) {
    __shared__ int sw[32];
    int tid = threadIdx.x, lane = tid & 31, w = tid >> 5;
    int i = blockIdx.x * 1024 + tid;
    int v = (i < n) ? deg[i] : 0;
    v = warpSumI(v);
    if (lane == 0) sw[w] = v;
    __syncthreads();
    if (w == 0) {
        int t = sw[lane];
        t = warpSumI(t);
        if (lane == 0) bsum[blockIdx.x] = t;
    }
}

__global__ void scan_bsum_kernel(int* __restrict__ bsum, int nb) {
    __shared__ int sh[64];
    int tid = threadIdx.x, lane = tid & 31, w = tid >> 5;
    int v = (tid < nb) ? bsum[tid] : 0;
    int iv = warpInclScan(v, lane);
    __shared__ int wtot[2];
    if (lane == 31) wtot[w] = iv;
    __syncthreads();
    int offs = (w == 1) ? wtot[0] : 0;
    sh[tid] = iv + offs - v;
    __syncthreads();
    if (tid < nb) bsum[tid] = sh[tid];
}

__global__ void scan_final_kernel(const int* __restrict__ deg, const int* __restrict__ bsum,
                                  int* __restrict__ rowptr, int* __restrict__ cursor, int n) {
    __shared__ int sw[32];
    int tid = threadIdx.x, lane = tid & 31, w = tid >> 5;
    int i = blockIdx.x * 1024 + tid;
    int v = (i < n) ? deg[i] : 0;
    int iv = warpInclScan(v, lane);
    if (lane == 31) sw[w] = iv;
    __syncthreads();
    if (w == 0) {
        int t = sw[lane];
        t = warpInclScan(t, lane);
        sw[lane] = t;
    }
    __syncthreads();
    int offs = ((w > 0) ? sw[w - 1] : 0) + bsum[blockIdx.x];
    int incl = iv + offs;
    if (i < n) {
        rowptr[i + 1] = incl;
        cursor[i] = incl - v;
    }
    if (i == 0) rowptr[0] = 0;
}

__global__ void scatter_kernel(const int* __restrict__ src, const int* __restrict__ dst,
                               int* __restrict__ cursor, int* __restrict__ ecol, int E) {
    int i = blockIdx.x * blockDim.x + threadIdx.x;
    if (i >= E) return;
    int pos = atomicAdd(&cursor[dst[i]], 1);
    ecol[pos] = src[i];
}

// ---------------- GEMM 128x128 (8x8/thread): C = A[M,K]*B[Nc,K]^T, Nc=256 -------------
// fused score epilogue: block column tile covers heads {2bx, 2bx+1}; each thread owns
// cols {tc*4..+3} of head 2bx and {64+tc*4..+3} of head 2bx+1.
#define QBM 128
#define QBK 16
__global__ void __launch_bounds__(256) gemm_nt128(
        const float* __restrict__ A, const float* __restrict__ B,
        float* __restrict__ C, int M, int Nc, int K,
        const float* __restrict__ as_, const float* __restrict__ ad_,
        float* __restrict__ s_, float* __restrict__ d_, int H) {
    __shared__ float As[QBK][QBM + 4];
    __shared__ float Bs[QBK][QBM + 4];
    int tid = threadIdx.x;
    int lane = tid & 31;
    int brow = blockIdx.y * QBM, bcol = blockIdx.x * 128;
    int tr = tid >> 4, tc = tid & 15;           // 16x16 thread grid
    float acc[8][8];
    #pragma unroll
    for (int i = 0; i < 8; i++)
        #pragma unroll
        for (int j = 0; j < 8; j++) acc[i][j] = 0.f;

    for (int k0 = 0; k0 < K; k0 += QBK) {
        #pragma unroll
        for (int t = 0; t < 2; t++) {
            int li = tid + t * 256;              // 512 float4 for A (128x16)
            int row = li >> 2, kq = (li & 3) * 4;
            int gm = brow + row;
            float4 v = make_float4(0.f, 0.f, 0.f, 0.f);
            if (gm < M) v = *(const float4*)&A[(size_t)gm * K + k0 + kq];
            As[kq + 0][row] = v.x; As[kq + 1][row] = v.y;
            As[kq + 2][row] = v.z; As[kq + 3][row] = v.w;
        }
        #pragma unroll
        for (int t = 0; t < 2; t++) {
            int li = tid + t * 256;              // 512 float4 for B (128x16)
            int row = li >> 2, kq = (li & 3) * 4;
            int gn = bcol + row;
            float4 v = make_float4(0.f, 0.f, 0.f, 0.f);
            if (gn < Nc) v = *(const float4*)&B[(size_t)gn * K + k0 + kq];
            Bs[kq + 0][row] = v.x; Bs[kq + 1][row] = v.y;
            Bs[kq + 2][row] = v.z; Bs[kq + 3][row] = v.w;
        }
        __syncthreads();
        #pragma unroll
        for (int kk = 0; kk < QBK; kk++) {
            float a[8], b[8];
            *(float4*)&a[0] = *(float4*)&As[kk][tr * 8];
            *(float4*)&a[4] = *(float4*)&As[kk][tr * 8 + 4];
            *(float4*)&b[0] = *(float4*)&Bs[kk][tc * 4];
            *(float4*)&b[4] = *(float4*)&Bs[kk][64 + tc * 4];
            #pragma unroll
            for (int i = 0; i < 8; i++)
                #pragma unroll
                for (int j = 0; j < 8; j++) acc[i][j] += a[i] * b[j];
        }
        __syncthreads();
    }

    // store C: per row, two float4 groups 64 cols apart
    #pragma unroll
    for (int i = 0; i < 8; i++) {
        int gm = brow + tr * 8 + i;
        if (gm >= M) continue;
        *(float4*)&C[(size_t)gm * Nc + bcol + tc * 4] =
            make_float4(acc[i][0], acc[i][1], acc[i][2], acc[i][3]);
        *(float4*)&C[(size_t)gm * Nc + bcol + 64 + tc * 4] =
            make_float4(acc[i][4], acc[i][5], acc[i][6], acc[i][7]);
    }

    // fused score epilogue (two heads per block)
    int h0 = blockIdx.x * 2, h1 = h0 + 1;
    float as0[4], ad0[4], as1[4], ad1[4];
    #pragma unroll
    for (int j = 0; j < 4; j++) {
        as0[j] = as_[h0 * 64 + tc * 4 + j];
        ad0[j] = ad_[h0 * 64 + tc * 4 + j];
        as1[j] = as_[h1 * 64 + tc * 4 + j];
        ad1[j] = ad_[h1 * 64 + tc * 4 + j];
    }
    #pragma unroll
    for (int i = 0; i < 8; i++) {
        float s0 = 0.f, e0 = 0.f, s1 = 0.f, e1 = 0.f;
        #pragma unroll
        for (int j = 0; j < 4; j++) {
            s0 += acc[i][j] * as0[j];
            e0 += acc[i][j] * ad0[j];
            s1 += acc[i][4 + j] * as1[j];
            e1 += acc[i][4 + j] * ad1[j];
        }
        #pragma unroll
        for (int o = 8; o >= 1; o >>= 1) {
            s0 += __shfl_xor_sync(0xffffffffu, s0, o);
            e0 += __shfl_xor_sync(0xffffffffu, e0, o);
            s1 += __shfl_xor_sync(0xffffffffu, s1, o);
            e1 += __shfl_xor_sync(0xffffffffu, e1, o);
        }
        int gm = brow + tr * 8 + i;
        if ((lane & 15) == 0 && gm < M) {
            s_[(size_t)gm * H + h0] = s0;
            d_[(size_t)gm * H + h0] = e0;
            s_[(size_t)gm * H + h1] = s1;
            d_[(size_t)gm * H + h1] = e1;
        }
    }
}

// ---------------- GEMM 128x64 (8x4/thread) for Nc=64, single-head epilogue -------------
#define GBM 128
#define GBN 64
#define GBK 16
__global__ void gemm_nt(const float* __restrict__ A, const float* __restrict__ B,
                        float* __restrict__ C, int M, int Nc, int K,
                        const float* __restrict__ as_, const float* __restrict__ ad_,
                        float* __restrict__ s_, float* __restrict__ d_, int H) {
    __shared__ float As[GBK][GBM + 4];
    __shared__ float Bs[GBK][GBN + 4];
    int tid = threadIdx.x;
    int brow = blockIdx.y * GBM;
    int bcol = blockIdx.x * GBN;
    int tr = tid >> 4, tc = tid & 15;
    float acc[8][4];
    #pragma unroll
    for (int i = 0; i < 8; i++)
        #pragma unroll
        for (int j = 0; j < 4; j++) acc[i][j] = 0.f;

    for (int k0 = 0; k0 < K; k0 += GBK) {
        #pragma unroll
        for (int t = 0; t < 2; t++) {
            int li = tid + t * 256;
            int row = li >> 2, kq = (li & 3) * 4;
            int gm = brow + row;
            float4 v = make_float4(0.f, 0.f, 0.f, 0.f);
            if (gm < M) v = *(const float4*)&A[(size_t)gm * K + k0 + kq];
            As[kq + 0][row] = v.x; As[kq + 1][row] = v.y;
            As[kq + 2][row] = v.z; As[kq + 3][row] = v.w;
        }
        {
            int li = tid;
            int row = li >> 2, kq = (li & 3) * 4;
            int gn = bcol + row;
            float4 v = make_float4(0.f, 0.f, 0.f, 0.f);
            if (gn < Nc) v = *(const float4*)&B[(size_t)gn * K + k0 + kq];
            Bs[kq + 0][row] = v.x; Bs[kq + 1][row] = v.y;
            Bs[kq + 2][row] = v.z; Bs[kq + 3][row] = v.w;
        }
        __syncthreads();
        #pragma unroll
        for (int kk = 0; kk < GBK; kk++) {
            float a[8], b[4];
            *(float4*)&a[0] = *(float4*)&As[kk][tr * 8];
            *(float4*)&a[4] = *(float4*)&As[kk][tr * 8 + 4];
            *(float4*)&b[0] = *(float4*)&Bs[kk][tc * 4];
            #pragma unroll
            for (int i = 0; i < 8; i++)
                #pragma unroll
                for (int j = 0; j < 4; j++) acc[i][j] += a[i] * b[j];
        }
        __syncthreads();
    }

    #pragma unroll
    for (int i = 0; i < 8; i++) {
        int gm = brow + tr * 8 + i;
        if (gm >= M) continue;
        #pragma unroll
        for (int j = 0; j < 4; j++) {
            int gn = bcol + tc * 4 + j;
            if (gn < Nc) C[(size_t)gm * Nc + gn] = acc[i][j];
        }
    }

    int head = blockIdx.x;
    float asv[4], adv[4];
    #pragma unroll
    for (int j = 0; j < 4; j++) {
        asv[j] = as_[head * 64 + tc * 4 + j];
        adv[j] = ad_[head * 64 + tc * 4 + j];
    }
    #pragma unroll
    for (int i = 0; i < 8; i++) {
        float ss = 0.f, dd = 0.f;
        #pragma unroll
        for (int j = 0; j < 4; j++) {
            ss += acc[i][j] * asv[j];
            dd += acc[i][j] * adv[j];
        }
        #pragma unroll
        for (int o = 8; o >= 1; o >>= 1) {
            ss += __shfl_xor_sync(0xffffffffu, ss, o);
            dd += __shfl_xor_sync(0xffffffffu, dd, o);
        }
        int gm = brow + tr * 8 + i;
        if ((tid & 15) == 0 && gm < M) {
            s_[(size_t)gm * H + head] = ss;
            d_[(size_t)gm * H + head] = dd;
        }
    }
}

// ---------------- fused per-dst: softmax + aggregate + bias/ELU + LayerNorm ------------
template<int H>
__global__ void gat_fused(const int* __restrict__ rowptr, const int* __restrict__ ecol,
                          const float* __restrict__ s_, const float* __restrict__ d_,
                          const float* __restrict__ h, const float* __restrict__ bias,
                          const float* __restrict__ lw, const float* __restrict__ lb,
                          float* __restrict__ outp, int n, int do_elu) {
    const int D = H * 64;
    const int NV = D / 32;
    int warp = (blockIdx.x * blockDim.x + threadIdx.x) >> 5;
    int lane = threadIdx.x & 31;
    if (warp >= n) return;
    int node = warp;
    int start = rowptr[node], end = rowptr[node + 1];

    float dsel[H], selfv[H];
    #pragma unroll
    for (int q = 0; q < H; q++) {
        float sv = s_[(size_t)node * H + q];
        float dv = d_[(size_t)node * H + q];
        dsel[q] = dv;
        selfv[q] = leaky(sv + dv);
    }
    float mx[H];
    #pragma unroll
    for (int q = 0; q < H; q++) mx[q] = selfv[q];
    for (int e = start + lane; e < end; e += 32) {
        int src = ecol[e];
        #pragma unroll
        for (int q = 0; q < H; q++) {
            float v = leaky(s_[(size_t)src * H + q] + dsel[q]);
            mx[q] = fmaxf(mx[q], v);
        }
    }
    #pragma unroll
    for (int q = 0; q < H; q++)
        #pragma unroll
        for (int o = 16; o > 0; o >>= 1) mx[q] = fmaxf(mx[q], __shfl_xor_sync(0xffffffffu, mx[q], o));

    float sm[H];
    #pragma unroll
    for (int q = 0; q < H; q++) sm[q] = 0.f;
    for (int e = start + lane; e < end; e += 32) {
        int src = ecol[e];
        #pragma unroll
        for (int q = 0; q < H; q++) {
            float v = leaky(s_[(size_t)src * H + q] + dsel[q]);
            sm[q] += expf(v - mx[q]);
        }
    }
    float inv[H], aself[H];
    #pragma unroll
    for (int q = 0; q < H; q++) {
        float tot = warpSum(sm[q]) + expf(selfv[q] - mx[q]);
        inv[q] = 1.f / (tot + 1e-16f);
        aself[q] = expf(selfv[q] - mx[q]) * inv[q];
    }

    int hl = lane & 3;
    float d_hl, m_hl, i_hl;
    if (H == 4) {
        d_hl = (hl == 0) ? dsel[0] : (hl == 1) ? dsel[1] : (hl == 2) ? dsel[2] : dsel[3];
        m_hl = (hl == 0) ? mx[0]   : (hl == 1) ? mx[1]   : (hl == 2) ? mx[2]   : mx[3];
        i_hl = (hl == 0) ? inv[0]  : (hl == 1) ? inv[1]  : (hl == 2) ? inv[2]  : inv[3];
    } else {
        d_hl = dsel[0]; m_hl = mx[0]; i_hl = inv[0];
    }

    float accv[NV];
    const float* hps = h + (size_t)node * D;
    #pragma unroll
    for (int i = 0; i < NV; i++) accv[i] = hps[lane + i * 32] * aself[i >> 1];

    for (int e0 = start; e0 < end; e0 += 8) {
        int me = e0 + (lane >> 2);
        float alpha = 0.f;
        int msrc = 0;
        if (me < end && hl < H) {
            msrc = ecol[me];
            float v = leaky(s_[(size_t)msrc * H + hl] + d_hl);
            alpha = expf(v - m_hl) * i_hl;
        }
        int cnt = end - e0; if (cnt > 8) cnt = 8;
        for (int j = 0; j < cnt; j++) {
            int src = __shfl_sync(0xffffffffu, msrc, j * 4);
            const float* hp = h + (size_t)src * D;
            #pragma unroll
            for (int i = 0; i < NV; i++) {
                float al = __shfl_sync(0xffffffffu, alpha, j * 4 + (i >> 1));
                accv[i] += hp[lane + i * 32] * al;
            }
        }
    }

    float ssum = 0.f;
    #pragma unroll
    for (int i = 0; i < NV; i++) {
        int cidx = lane + i * 32;
        float v = accv[i] + bias[cidx];
        if (do_elu) v = v > 0.f ? v : (expf(v) - 1.f);
        accv[i] = v;
        ssum += v;
    }
    ssum = warpSum(ssum);
    float mu = ssum / (float)D;
    float vs = 0.f;
    #pragma unroll
    for (int i = 0; i < NV; i++) { float t = accv[i] - mu; vs += t * t; }
    vs = warpSum(vs);
    float rs = rsqrtf(vs / (float)D + 1e-5f);
    float* orow = outp + (size_t)node * D;
    #pragma unroll
    for (int i = 0; i < NV; i++) {
        int cidx = lane + i * 32;
        orow[cidx] = (accv[i] - mu) * rs * lw[cidx] + lb[cidx];
    }
}

// ---------------- final MLP head ----------------
__global__ void head_kernel(const float* __restrict__ h3, const int* __restrict__ role,
                            const float* __restrict__ rt, const float* __restrict__ p1w,
                            const float* __restrict__ p1b, const float* __restrict__ p2w,
                            const float* __restrict__ p2b, float* __restrict__ z, int n) {
    extern __shared__ float sm[];
    float* sp1 = sm;
    float* sp2 = sp1 + 128 * 64;
    float* sz  = sp2 + 64 * 64;
    float* sz1 = sz + 4 * 128;
    int tid = threadIdx.x;
    for (int i = tid; i < 128 * 64; i += 256) {
        int j = i / 128, k = i % 128;
        sp1[k * 64 + j] = p1w[i];
    }
    for (int i = tid; i < 64 * 64; i += 256) {
        int j = i / 64, k = i % 64;
        sp2[k * 64 + j] = p2w[i];
    }
    __syncthreads();
    int g = tid >> 6, j = tid & 63;
    float b1v = p1b[j], b2v = p2b[j];
    for (int it = 0; it < 16; it++) {
        int node = blockIdx.x * 64 + it * 4 + g;
        bool valid = node < n;
        if (valid) {
            sz[g * 128 + j] = h3[(size_t)node * 64 + j];
            int r = role[node];
            sz[g * 128 + 64 + j] = rt[r * 64 + j];
        }
        __syncthreads();
        float acc = b1v;
        #pragma unroll 8
        for (int k = 0; k < 128; k++) acc += sp1[k * 64 + j] * sz[g * 128 + k];
        sz1[g * 64 + j] = fmaxf(acc, 0.f);
        __syncthreads();
        float acc2 = b2v;
        #pragma unroll 8
        for (int k = 0; k < 64; k++) acc2 += sp2[k * 64 + j] * sz1[g * 64 + k];
        if (valid) z[(size_t)node * 64 + j] = acc2;
    }
}

// ---------------- host orchestration ----------------
extern "C" void kernel_launch(void* const* d_in, const int* in_sizes, int n_in,
                              void* d_out, int out_size) {
    const float* x   = (const float*)d_in[0];
    const void*  ei  = d_in[1];
    const void*  rid = d_in[2];
    const float* W1  = (const float*)d_in[3];
    const float* a1s = (const float*)d_in[4];
    const float* a1d = (const float*)d_in[5];
    const float* b1  = (const float*)d_in[6];
    const float* W2  = (const float*)d_in[7];
    const float* a2s = (const float*)d_in[8];
    const float* a2d = (const float*)d_in[9];
    const float* b2  = (const float*)d_in[10];
    const float* W3  = (const float*)d_in[11];
    const float* a3s = (const float*)d_in[12];
    const float* a3d = (const float*)d_in[13];
    const float* b3  = (const float*)d_in[14];
    const float* ln1w = (const float*)d_in[15];
    const float* ln1b = (const float*)d_in[16];
    const float* ln2w = (const float*)d_in[17];
    const float* ln2b = (const float*)d_in[18];
    const float* ln3w = (const float*)d_in[19];
    const float* ln3b = (const float*)d_in[20];
    const float* rt   = (const float*)d_in[21];
    const float* p1w  = (const float*)d_in[22];
    const float* p1b  = (const float*)d_in[23];
    const float* p2w  = (const float*)d_in[24];
    const float* p2b  = (const float*)d_in[25];
    float* z = (float*)d_out;

    float *hbuf, *xbuf, *ybuf, *sp, *dp;
    int *srcp, *dstp, *ecolp, *rowp, *degp, *curp, *bsump, *rolep, *flagp;
    cudaGetSymbolAddress((void**)&hbuf, g_h);
    cudaGetSymbolAddress((void**)&xbuf, g_x);
    cudaGetSymbolAddress((void**)&ybuf, g_y);
    cudaGetSymbolAddress((void**)&sp, g_s);
    cudaGetSymbolAddress((void**)&dp, g_d);
    cudaGetSymbolAddress((void**)&srcp, g_src);
    cudaGetSymbolAddress((void**)&dstp, g_dst);
    cudaGetSymbolAddress((void**)&ecolp, g_ecol);
    cudaGetSymbolAddress((void**)&rowp, g_rowptr);
    cudaGetSymbolAddress((void**)&degp, g_deg);
    cudaGetSymbolAddress((void**)&curp, g_cursor);
    cudaGetSymbolAddress((void**)&bsump, g_bsum);
    cudaGetSymbolAddress((void**)&rolep, g_role);
    cudaGetSymbolAddress((void**)&flagp, g_is64);

    const int n = NN, E = EE;
    const int nb = (n + 1023) / 1024;

    detect_kernel<<<1, 32>>>((const unsigned int*)ei, flagp);
    cudaMemsetAsync(degp, 0, n * sizeof(int));
    prep_kernel<<<(E + 255) / 256, 256>>>(ei, rid, srcp, dstp, degp, rolep, flagp, E, n);
    scan_reduce_kernel<<<nb, 1024>>>(degp, bsump, n);
    scan_bsum_kernel<<<1, 64>>>(bsump, nb);
    scan_final_kernel<<<nb, 1024>>>(degp, bsump, rowp, curp, n);
    scatter_kernel<<<(E + 255) / 256, 256>>>(srcp, dstp, curp, ecolp, E);

    dim3 gq(256 / 128, (n + QBM - 1) / QBM);   // 128x128 tiles for Nc=256
    dim3 g3(64 / GBN, (n + GBM - 1) / GBM);    // 128x64 tiles for Nc=64
    int fusedBlocks = (n * 32 + 255) / 256;

    // layer 1: 64 -> 4x64 concat, elu + LN (scores fused in GEMM epilogue)
    gemm_nt128<<<gq, 256>>>(x, W1, hbuf, n, 256, 64, a1s, a1d, sp, dp, 4);
    gat_fused<4><<<fusedBlocks, 256>>>(rowp, ecolp, sp, dp, hbuf, b1, ln1w, ln1b, xbuf, n, 1);

    // layer 2: 256 -> 4x64 concat, elu + LN
    gemm_nt128<<<gq, 256>>>(xbuf, W2, hbuf, n, 256, 256, a2s, a2d, sp, dp, 4);
    gat_fused<4><<<fusedBlocks, 256>>>(rowp, ecolp, sp, dp, hbuf, b2, ln2w, ln2b, xbuf, n, 1);

    // layer 3: 256 -> 1x64, LN only
    gemm_nt<<<g3, 256>>>(xbuf, W3, hbuf, n, 64, 256, a3s, a3d, sp, dp, 1);
    gat_fused<1><<<fusedBlocks, 256>>>(rowp, ecolp, sp, dp, hbuf, b3, ln3w, ln3b, ybuf, n, 0);

    // final MLP head
    size_t smem = (128 * 64 + 64 * 64 + 4 * 128 + 4 * 64) * sizeof(float);
    cudaFuncSetAttribute(head_kernel, cudaFuncAttributeMaxDynamicSharedMemorySize, (int)smem);
    head_kernel<<<(n + 63) / 64, 256, smem>>>(ybuf, rolep, rt, p1w, p1b, p2w, p2b, z, n);
}

// round 7
// speedup vs baseline: 1.2282x; 1.0002x over previous
#include <cuda_runtime.h>
#include <math.h>

#define NN 50000
#define EE 400000
#define DMAX 256

// ---------------- scratch (static device globals; no allocation) ----------------
__device__ float g_h[(size_t)NN * DMAX];
__device__ float g_x[(size_t)NN * DMAX];
__device__ float g_y[(size_t)NN * DMAX];
__device__ float g_s[NN * 4];
__device__ float g_d[NN * 4];
__device__ int g_src[EE];
__device__ int g_dst[EE];
__device__ int g_ecol[EE];
__device__ int g_rowptr[NN + 1];
__device__ int g_deg[NN];
__device__ int g_cursor[NN];
__device__ int g_bsum[64];
__device__ int g_role[NN];
__device__ int g_is64;

// ---------------- helpers ----------------
__device__ __forceinline__ float warpSum(float v) {
    #pragma unroll
    for (int o = 16; o > 0; o >>= 1) v += __shfl_xor_sync(0xffffffffu, v, o);
    return v;
}
__device__ __forceinline__ int warpSumI(int v) {
    #pragma unroll
    for (int o = 16; o > 0; o >>= 1) v += __shfl_xor_sync(0xffffffffu, v, o);
    return v;
}
__device__ __forceinline__ int warpInclScan(int v, int lane) {
    #pragma unroll
    for (int o = 1; o < 32; o <<= 1) {
        int t = __shfl_up_sync(0xffffffffu, v, o);
        if (lane >= o) v += t;
    }
    return v;
}
__device__ __forceinline__ float leaky(float v) { return v > 0.f ? v : 0.2f * v; }

// ---------------- dtype detect + prep ----------------
__global__ void detect_kernel(const unsigned int* __restrict__ w, int* flag) {
    if (threadIdx.x == 0 && blockIdx.x == 0) {
        int is64 = 1;
        for (int i = 0; i < 64; i++)
            if (w[2 * i + 1] != 0u) { is64 = 0; break; }
        *flag = is64;
    }
}

__global__ void prep_kernel(const void* __restrict__ ei, const void* __restrict__ rid,
                            int* __restrict__ src, int* __restrict__ dst,
                            int* __restrict__ deg, int* __restrict__ role,
                            const int* __restrict__ flag, int E, int n) {
    int i = blockIdx.x * blockDim.x + threadIdx.x;
    int is64 = *flag;
    if (i < E) {
        int s, d;
        if (is64) {
            const long long* p = (const long long*)ei;
            s = (int)p[i];
            d = (int)p[(size_t)E + i];
        } else {
            const int* p = (const int*)ei;
            s = p[i];
            d = p[E + i];
        }
        src[i] = s;
        dst[i] = d;
        atomicAdd(&deg[d], 1);
    }
    if (i < n) {
        if (is64) role[i] = (int)((const long long*)rid)[i];
        else      role[i] = ((const int*)rid)[i];
    }
}

// ---------------- 2-phase scan (block sums + final with local bsum prefix) -----------
__global__ void scan_reduce_kernel(const int* __restrict__ deg, int* __restrict__ bsum, int n) {
    __shared__ int sw[32];
    int tid = threadIdx.x, lane = tid & 31, w = tid >> 5;
    int i = blockIdx.x * 1024 + tid;
    int v = (i < n) ? deg[i] : 0;
    v = warpSumI(v);
    if (lane == 0) sw[w] = v;
    __syncthreads();
    if (w == 0) {
        int t = sw[lane];
        t = warpSumI(t);
        if (lane == 0) bsum[blockIdx.x] = t;
    }
}

__global__ void scan_final_kernel(const int* __restrict__ deg, const int* __restrict__ bsum,
                                  int* __restrict__ rowptr, int* __restrict__ cursor, int n) {
    __shared__ int sw[32];
    __shared__ int partial[2];
    int tid = threadIdx.x, lane = tid & 31, w = tid >> 5;
    int bid = blockIdx.x;
    // local prefix over previous block sums (nb <= 64)
    if (tid < 64) {
        int v = (tid < bid) ? bsum[tid] : 0;
        v = warpSumI(v);
        if ((tid & 31) == 0) partial[tid >> 5] = v;
    }
    int i = bid * 1024 + tid;
    int v = (i < n) ? deg[i] : 0;
    int iv = warpInclScan(v, lane);
    if (lane == 31) sw[w] = iv;
    __syncthreads();
    int base = partial[0] + partial[1];
    if (w == 0) {
        int t = sw[lane];
        t = warpInclScan(t, lane);
        sw[lane] = t;
    }
    __syncthreads();
    int offs = ((w > 0) ? sw[w - 1] : 0) + base;
    int incl = iv + offs;
    if (i < n) {
        rowptr[i + 1] = incl;
        cursor[i] = incl - v;
    }
    if (i == 0) rowptr[0] = 0;
}

__global__ void scatter_kernel(const int* __restrict__ src, const int* __restrict__ dst,
                               int* __restrict__ cursor, int* __restrict__ ecol, int E) {
    int i = blockIdx.x * blockDim.x + threadIdx.x;
    if (i >= E) return;
    int pos = atomicAdd(&cursor[dst[i]], 1);
    ecol[pos] = src[i];
}

// ---------------- pipelined GEMM 128x128 (8x8/thread), Nc=256, fused score epilogue ---
#define QBM 128
#define QBK 16
__global__ void __launch_bounds__(256, 2) gemm_nt128(
        const float* __restrict__ A, const float* __restrict__ B,
        float* __restrict__ C, int M, int Nc, int K,
        const float* __restrict__ as_, const float* __restrict__ ad_,
        float* __restrict__ s_, float* __restrict__ d_, int H) {
    __shared__ float As[2][QBK][QBM + 4];
    __shared__ float Bs[2][QBK][QBM + 4];
    int tid = threadIdx.x;
    int lane = tid & 31;
    int brow = blockIdx.y * QBM, bcol = blockIdx.x * 128;
    int tr = tid >> 4, tc = tid & 15;
    float acc[8][8];
    #pragma unroll
    for (int i = 0; i < 8; i++)
        #pragma unroll
        for (int j = 0; j < 8; j++) acc[i][j] = 0.f;

    // load geometry: li = tid + t*256 -> row = li>>2, kq = (li&3)*4
    int lrow[2], lkq[2];
    #pragma unroll
    for (int t = 0; t < 2; t++) { int li = tid + t * 256; lrow[t] = li >> 2; lkq[t] = (li & 3) * 4; }

    float4 aReg[2], bReg[2];
    const int nch = K / QBK;

    // prologue: LDG + STS chunk 0
    #pragma unroll
    for (int t = 0; t < 2; t++) {
        int gm = brow + lrow[t];
        aReg[t] = (gm < M) ? *(const float4*)&A[(size_t)gm * K + lkq[t]]
                           : make_float4(0.f, 0.f, 0.f, 0.f);
        int gn = bcol + lrow[t];
        bReg[t] = (gn < Nc) ? *(const float4*)&B[(size_t)gn * K + lkq[t]]
                            : make_float4(0.f, 0.f, 0.f, 0.f);
    }
    #pragma unroll
    for (int t = 0; t < 2; t++) {
        As[0][lkq[t] + 0][lrow[t]] = aReg[t].x; As[0][lkq[t] + 1][lrow[t]] = aReg[t].y;
        As[0][lkq[t] + 2][lrow[t]] = aReg[t].z; As[0][lkq[t] + 3][lrow[t]] = aReg[t].w;
        Bs[0][lkq[t] + 0][lrow[t]] = bReg[t].x; Bs[0][lkq[t] + 1][lrow[t]] = bReg[t].y;
        Bs[0][lkq[t] + 2][lrow[t]] = bReg[t].z; Bs[0][lkq[t] + 3][lrow[t]] = bReg[t].w;
    }
    __syncthreads();

    for (int c = 0; c < nch; c++) {
        int buf = c & 1;
        if (c + 1 < nch) {
            int k0 = (c + 1) * QBK;
            #pragma unroll
            for (int t = 0; t < 2; t++) {
                int gm = brow + lrow[t];
                aReg[t] = (gm < M) ? *(const float4*)&A[(size_t)gm * K + k0 + lkq[t]]
                                   : make_float4(0.f, 0.f, 0.f, 0.f);
                int gn = bcol + lrow[t];
                bReg[t] = (gn < Nc) ? *(const float4*)&B[(size_t)gn * K + k0 + lkq[t]]
                                    : make_float4(0.f, 0.f, 0.f, 0.f);
            }
        }
        #pragma unroll
        for (int kk = 0; kk < QBK; kk++) {
            float a[8], b[8];
            *(float4*)&a[0] = *(float4*)&As[buf][kk][tr * 8];
            *(float4*)&a[4] = *(float4*)&As[buf][kk][tr * 8 + 4];
            *(float4*)&b[0] = *(float4*)&Bs[buf][kk][tc * 4];
            *(float4*)&b[4] = *(float4*)&Bs[buf][kk][64 + tc * 4];
            #pragma unroll
            for (int i = 0; i < 8; i++)
                #pragma unroll
                for (int j = 0; j < 8; j++) acc[i][j] += a[i] * b[j];
        }
        if (c + 1 < nch) {
            int nb = buf ^ 1;
            #pragma unroll
            for (int t = 0; t < 2; t++) {
                As[nb][lkq[t] + 0][lrow[t]] = aReg[t].x; As[nb][lkq[t] + 1][lrow[t]] = aReg[t].y;
                As[nb][lkq[t] + 2][lrow[t]] = aReg[t].z; As[nb][lkq[t] + 3][lrow[t]] = aReg[t].w;
                Bs[nb][lkq[t] + 0][lrow[t]] = bReg[t].x; Bs[nb][lkq[t] + 1][lrow[t]] = bReg[t].y;
                Bs[nb][lkq[t] + 2][lrow[t]] = bReg[t].z; Bs[nb][lkq[t] + 3][lrow[t]] = bReg[t].w;
            }
        }
        __syncthreads();
    }

    // store C
    #pragma unroll
    for (int i = 0; i < 8; i++) {
        int gm = brow + tr * 8 + i;
        if (gm >= M) continue;
        *(float4*)&C[(size_t)gm * Nc + bcol + tc * 4] =
            make_float4(acc[i][0], acc[i][1], acc[i][2], acc[i][3]);
        *(float4*)&C[(size_t)gm * Nc + bcol + 64 + tc * 4] =
            make_float4(acc[i][4], acc[i][5], acc[i][6], acc[i][7]);
    }

    // fused score epilogue (two heads per block)
    int h0 = blockIdx.x * 2, h1 = h0 + 1;
    float as0[4], ad0[4], as1[4], ad1[4];
    #pragma unroll
    for (int j = 0; j < 4; j++) {
        as0[j] = as_[h0 * 64 + tc * 4 + j];
        ad0[j] = ad_[h0 * 64 + tc * 4 + j];
        as1[j] = as_[h1 * 64 + tc * 4 + j];
        ad1[j] = ad_[h1 * 64 + tc * 4 + j];
    }
    #pragma unroll
    for (int i = 0; i < 8; i++) {
        float s0 = 0.f, e0 = 0.f, s1 = 0.f, e1 = 0.f;
        #pragma unroll
        for (int j = 0; j < 4; j++) {
            s0 += acc[i][j] * as0[j];
            e0 += acc[i][j] * ad0[j];
            s1 += acc[i][4 + j] * as1[j];
            e1 += acc[i][4 + j] * ad1[j];
        }
        #pragma unroll
        for (int o = 8; o >= 1; o >>= 1) {
            s0 += __shfl_xor_sync(0xffffffffu, s0, o);
            e0 += __shfl_xor_sync(0xffffffffu, e0, o);
            s1 += __shfl_xor_sync(0xffffffffu, s1, o);
            e1 += __shfl_xor_sync(0xffffffffu, e1, o);
        }
        int gm = brow + tr * 8 + i;
        if ((lane & 15) == 0 && gm < M) {
            s_[(size_t)gm * H + h0] = s0;
            d_[(size_t)gm * H + h0] = e0;
            s_[(size_t)gm * H + h1] = s1;
            d_[(size_t)gm * H + h1] = e1;
        }
    }
}

// ---------------- pipelined GEMM 128x64 (8x4/thread), Nc=64, single-head epilogue ------
#define GBM 128
#define GBN 64
#define GBK 16
__global__ void __launch_bounds__(256) gemm_nt(
        const float* __restrict__ A, const float* __restrict__ B,
        float* __restrict__ C, int M, int Nc, int K,
        const float* __restrict__ as_, const float* __restrict__ ad_,
        float* __restrict__ s_, float* __restrict__ d_, int H) {
    __shared__ float As[2][GBK][GBM + 4];
    __shared__ float Bs[2][GBK][GBN + 4];
    int tid = threadIdx.x;
    int brow = blockIdx.y * GBM;
    int bcol = blockIdx.x * GBN;
    int tr = tid >> 4, tc = tid & 15;
    float acc[8][4];
    #pragma unroll
    for (int i = 0; i < 8; i++)
        #pragma unroll
        for (int j = 0; j < 4; j++) acc[i][j] = 0.f;

    int lrow[2], lkq[2];
    #pragma unroll
    for (int t = 0; t < 2; t++) { int li = tid + t * 256; lrow[t] = li >> 2; lkq[t] = (li & 3) * 4; }
    float4 aReg[2], bReg;
    const int nch = K / GBK;

    #pragma unroll
    for (int t = 0; t < 2; t++) {
        int gm = brow + lrow[t];
        aReg[t] = (gm < M) ? *(const float4*)&A[(size_t)gm * K + lkq[t]]
                           : make_float4(0.f, 0.f, 0.f, 0.f);
    }
    {
        int gn = bcol + lrow[0];
        bReg = (gn < Nc) ? *(const float4*)&B[(size_t)gn * K + lkq[0]]
                         : make_float4(0.f, 0.f, 0.f, 0.f);
    }
    #pragma unroll
    for (int t = 0; t < 2; t++) {
        As[0][lkq[t] + 0][lrow[t]] = aReg[t].x; As[0][lkq[t] + 1][lrow[t]] = aReg[t].y;
        As[0][lkq[t] + 2][lrow[t]] = aReg[t].z; As[0][lkq[t] + 3][lrow[t]] = aReg[t].w;
    }
    Bs[0][lkq[0] + 0][lrow[0]] = bReg.x; Bs[0][lkq[0] + 1][lrow[0]] = bReg.y;
    Bs[0][lkq[0] + 2][lrow[0]] = bReg.z; Bs[0][lkq[0] + 3][lrow[0]] = bReg.w;
    __syncthreads();

    for (int c = 0; c < nch; c++) {
        int buf = c & 1;
        if (c + 1 < nch) {
            int k0 = (c + 1) * GBK;
            #pragma unroll
            for (int t = 0; t < 2; t++) {
                int gm = brow + lrow[t];
                aReg[t] = (gm < M) ? *(const float4*)&A[(size_t)gm * K + k0 + lkq[t]]
                                   : make_float4(0.f, 0.f, 0.f, 0.f);
            }
            int gn = bcol + lrow[0];
            bReg = (gn < Nc) ? *(const float4*)&B[(size_t)gn * K + k0 + lkq[0]]
                             : make_float4(0.f, 0.f, 0.f, 0.f);
        }
        #pragma unroll
        for (int kk = 0; kk < GBK; kk++) {
            float a[8], b[4];
            *(float4*)&a[0] = *(float4*)&As[buf][kk][tr * 8];
            *(float4*)&a[4] = *(float4*)&As[buf][kk][tr * 8 + 4];
            *(float4*)&b[0] = *(float4*)&Bs[buf][kk][tc * 4];
            #pragma unroll
            for (int i = 0; i < 8; i++)
                #pragma unroll
                for (int j = 0; j < 4; j++) acc[i][j] += a[i] * b[j];
        }
        if (c + 1 < nch) {
            int nb = buf ^ 1;
            #pragma unroll
            for (int t = 0; t < 2; t++) {
                As[nb][lkq[t] + 0][lrow[t]] = aReg[t].x; As[nb][lkq[t] + 1][lrow[t]] = aReg[t].y;
                As[nb][lkq[t] + 2][lrow[t]] = aReg[t].z; As[nb][lkq[t] + 3][lrow[t]] = aReg[t].w;
            }
            Bs[nb][lkq[0] + 0][lrow[0]] = bReg.x; Bs[nb][lkq[0] + 1][lrow[0]] = bReg.y;
            Bs[nb][lkq[0] + 2][lrow[0]] = bReg.z; Bs[nb][lkq[0] + 3][lrow[0]] = bReg.w;
        }
        __syncthreads();
    }

    #pragma unroll
    for (int i = 0; i < 8; i++) {
        int gm = brow + tr * 8 + i;
        if (gm >= M) continue;
        #pragma unroll
        for (int j = 0; j < 4; j++) {
            int gn = bcol + tc * 4 + j;
            if (gn < Nc) C[(size_t)gm * Nc + gn] = acc[i][j];
        }
    }

    int head = blockIdx.x;
    float asv[4], adv[4];
    #pragma unroll
    for (int j = 0; j < 4; j++) {
        asv[j] = as_[head * 64 + tc * 4 + j];
        adv[j] = ad_[head * 64 + tc * 4 + j];
    }
    #pragma unroll
    for (int i = 0; i < 8; i++) {
        float ss = 0.f, dd = 0.f;
        #pragma unroll
        for (int j = 0; j < 4; j++) {
            ss += acc[i][j] * asv[j];
            dd += acc[i][j] * adv[j];
        }
        #pragma unroll
        for (int o = 8; o >= 1; o >>= 1) {
            ss += __shfl_xor_sync(0xffffffffu, ss, o);
            dd += __shfl_xor_sync(0xffffffffu, dd, o);
        }
        int gm = brow + tr * 8 + i;
        if ((tid & 15) == 0 && gm < M) {
            s_[(size_t)gm * H + head] = ss;
            d_[(size_t)gm * H + head] = dd;
        }
    }
}

// ---------------- fused per-dst: softmax + aggregate + bias/ELU + LayerNorm ------------
template<int H>
__global__ void gat_fused(const int* __restrict__ rowptr, const int* __restrict__ ecol,
                          const float* __restrict__ s_, const float* __restrict__ d_,
                          const float* __restrict__ h, const float* __restrict__ bias,
                          const float* __restrict__ lw, const float* __restrict__ lb,
                          float* __restrict__ outp, int n, int do_elu) {
    const int D = H * 64;
    const int NV = D / 32;
    int warp = (blockIdx.x * blockDim.x + threadIdx.x) >> 5;
    int lane = threadIdx.x & 31;
    if (warp >= n) return;
    int node = warp;
    int start = rowptr[node], end = rowptr[node + 1];

    float dsel[H], selfv[H];
    #pragma unroll
    for (int q = 0; q < H; q++) {
        float sv = s_[(size_t)node * H + q];
        float dv = d_[(size_t)node * H + q];
        dsel[q] = dv;
        selfv[q] = leaky(sv + dv);
    }
    float mx[H];
    #pragma unroll
    for (int q = 0; q < H; q++) mx[q] = selfv[q];
    for (int e = start + lane; e < end; e += 32) {
        int src = ecol[e];
        #pragma unroll
        for (int q = 0; q < H; q++) {
            float v = leaky(s_[(size_t)src * H + q] + dsel[q]);
            mx[q] = fmaxf(mx[q], v);
        }
    }
    #pragma unroll
    for (int q = 0; q < H; q++)
        #pragma unroll
        for (int o = 16; o > 0; o >>= 1) mx[q] = fmaxf(mx[q], __shfl_xor_sync(0xffffffffu, mx[q], o));

    float sm[H];
    #pragma unroll
    for (int q = 0; q < H; q++) sm[q] = 0.f;
    for (int e = start + lane; e < end; e += 32) {
        int src = ecol[e];
        #pragma unroll
        for (int q = 0; q < H; q++) {
            float v = leaky(s_[(size_t)src * H + q] + dsel[q]);
            sm[q] += expf(v - mx[q]);
        }
    }
    float inv[H], aself[H];
    #pragma unroll
    for (int q = 0; q < H; q++) {
        float tot = warpSum(sm[q]) + expf(selfv[q] - mx[q]);
        inv[q] = 1.f / (tot + 1e-16f);
        aself[q] = expf(selfv[q] - mx[q]) * inv[q];
    }

    int hl = lane & 3;
    float d_hl, m_hl, i_hl;
    if (H == 4) {
        d_hl = (hl == 0) ? dsel[0] : (hl == 1) ? dsel[1] : (hl == 2) ? dsel[2] : dsel[3];
        m_hl = (hl == 0) ? mx[0]   : (hl == 1) ? mx[1]   : (hl == 2) ? mx[2]   : mx[3];
        i_hl = (hl == 0) ? inv[0]  : (hl == 1) ? inv[1]  : (hl == 2) ? inv[2]  : inv[3];
    } else {
        d_hl = dsel[0]; m_hl = mx[0]; i_hl = inv[0];
    }

    float accv[NV];
    const float* hps = h + (size_t)node * D;
    #pragma unroll
    for (int i = 0; i < NV; i++) accv[i] = hps[lane + i * 32] * aself[i >> 1];

    for (int e0 = start; e0 < end; e0 += 8) {
        int me = e0 + (lane >> 2);
        float alpha = 0.f;
        int msrc = 0;
        if (me < end && hl < H) {
            msrc = ecol[me];
            float v = leaky(s_[(size_t)msrc * H + hl] + d_hl);
            alpha = expf(v - m_hl) * i_hl;
        }
        int cnt = end - e0; if (cnt > 8) cnt = 8;
        for (int j = 0; j < cnt; j++) {
            int src = __shfl_sync(0xffffffffu, msrc, j * 4);
            const float* hp = h + (size_t)src * D;
            #pragma unroll
            for (int i = 0; i < NV; i++) {
                float al = __shfl_sync(0xffffffffu, alpha, j * 4 + (i >> 1));
                accv[i] += hp[lane + i * 32] * al;
            }
        }
    }

    float ssum = 0.f;
    #pragma unroll
    for (int i = 0; i < NV; i++) {
        int cidx = lane + i * 32;
        float v = accv[i] + bias[cidx];
        if (do_elu) v = v > 0.f ? v : (expf(v) - 1.f);
        accv[i] = v;
        ssum += v;
    }
    ssum = warpSum(ssum);
    float mu = ssum / (float)D;
    float vs = 0.f;
    #pragma unroll
    for (int i = 0; i < NV; i++) { float t = accv[i] - mu; vs += t * t; }
    vs = warpSum(vs);
    float rs = rsqrtf(vs / (float)D + 1e-5f);
    float* orow = outp + (size_t)node * D;
    #pragma unroll
    for (int i = 0; i < NV; i++) {
        int cidx = lane + i * 32;
        orow[cidx] = (accv[i] - mu) * rs * lw[cidx] + lb[cidx];
    }
}

// ---------------- final MLP head ----------------
__global__ void head_kernel(const float* __restrict__ h3, const int* __restrict__ role,
                            const float* __restrict__ rt, const float* __restrict__ p1w,
                            const float* __restrict__ p1b, const float* __restrict__ p2w,
                            const float* __restrict__ p2b, float* __restrict__ z, int n) {
    extern __shared__ float sm[];
    float* sp1 = sm;
    float* sp2 = sp1 + 128 * 64;
    float* sz  = sp2 + 64 * 64;
    float* sz1 = sz + 4 * 128;
    int tid = threadIdx.x;
    for (int i = tid; i < 128 * 64; i += 256) {
        int j = i / 128, k = i % 128;
        sp1[k * 64 + j] = p1w[i];
    }
    for (int i = tid; i < 64 * 64; i += 256) {
        int j = i / 64, k = i % 64;
        sp2[k * 64 + j] = p2w[i];
    }
    __syncthreads();
    int g = tid >> 6, j = tid & 63;
    float b1v = p1b[j], b2v = p2b[j];
    for (int it = 0; it < 16; it++) {
        int node = blockIdx.x * 64 + it * 4 + g;
        bool valid = node < n;
        if (valid) {
            sz[g * 128 + j] = h3[(size_t)node * 64 + j];
            int r = role[node];
            sz[g * 128 + 64 + j] = rt[r * 64 + j];
        }
        __syncthreads();
        float acc = b1v;
        #pragma unroll 8
        for (int k = 0; k < 128; k++) acc += sp1[k * 64 + j] * sz[g * 128 + k];
        sz1[g * 64 + j] = fmaxf(acc, 0.f);
        __syncthreads();
        float acc2 = b2v;
        #pragma unroll 8
        for (int k = 0; k < 64; k++) acc2 += sp2[k * 64 + j] * sz1[g * 64 + k];
        if (valid) z[(size_t)node * 64 + j] = acc2;
    }
}

// ---------------- host orchestration ----------------
extern "C" void kernel_launch(void* const* d_in, const int* in_sizes, int n_in,
                              void* d_out, int out_size) {
    const float* x   = (const float*)d_in[0];
    const void*  ei  = d_in[1];
    const void*  rid = d_in[2];
    const float* W1  = (const float*)d_in[3];
    const float* a1s = (const float*)d_in[4];
    const float* a1d = (const float*)d_in[5];
    const float* b1  = (const float*)d_in[6];
    const float* W2  = (const float*)d_in[7];
    const float* a2s = (const float*)d_in[8];
    const float* a2d = (const float*)d_in[9];
    const float* b2  = (const float*)d_in[10];
    const float* W3  = (const float*)d_in[11];
    const float* a3s = (const float*)d_in[12];
    const float* a3d = (const float*)d_in[13];
    const float* b3  = (const float*)d_in[14];
    const float* ln1w = (const float*)d_in[15];
    const float* ln1b = (const float*)d_in[16];
    const float* ln2w = (const float*)d_in[17];
    const float* ln2b = (const float*)d_in[18];
    const float* ln3w = (const float*)d_in[19];
    const float* ln3b = (const float*)d_in[20];
    const float* rt   = (const float*)d_in[21];
    const float* p1w  = (const float*)d_in[22];
    const float* p1b  = (const float*)d_in[23];
    const float* p2w  = (const float*)d_in[24];
    const float* p2b  = (const float*)d_in[25];
    float* z = (float*)d_out;

    float *hbuf, *xbuf, *ybuf, *sp, *dp;
    int *srcp, *dstp, *ecolp, *rowp, *degp, *curp, *bsump, *rolep, *flagp;
    cudaGetSymbolAddress((void**)&hbuf, g_h);
    cudaGetSymbolAddress((void**)&xbuf, g_x);
    cudaGetSymbolAddress((void**)&ybuf, g_y);
    cudaGetSymbolAddress((void**)&sp, g_s);
    cudaGetSymbolAddress((void**)&dp, g_d);
    cudaGetSymbolAddress((void**)&srcp, g_src);
    cudaGetSymbolAddress((void**)&dstp, g_dst);
    cudaGetSymbolAddress((void**)&ecolp, g_ecol);
    cudaGetSymbolAddress((void**)&rowp, g_rowptr);
    cudaGetSymbolAddress((void**)&degp, g_deg);
    cudaGetSymbolAddress((void**)&curp, g_cursor);
    cudaGetSymbolAddress((void**)&bsump, g_bsum);
    cudaGetSymbolAddress((void**)&rolep, g_role);
    cudaGetSymbolAddress((void**)&flagp, g_is64);

    const int n = NN, E = EE;
    const int nb = (n + 1023) / 1024;

    detect_kernel<<<1, 32>>>((const unsigned int*)ei, flagp);
    cudaMemsetAsync(degp, 0, n * sizeof(int));
    prep_kernel<<<(E + 255) / 256, 256>>>(ei, rid, srcp, dstp, degp, rolep, flagp, E, n);
    scan_reduce_kernel<<<nb, 1024>>>(degp, bsump, n);
    scan_final_kernel<<<nb, 1024>>>(degp, bsump, rowp, curp, n);
    scatter_kernel<<<(E + 255) / 256, 256>>>(srcp, dstp, curp, ecolp, E);

    dim3 gq(256 / 128, (n + QBM - 1) / QBM);
    dim3 g3(64 / GBN, (n + GBM - 1) / GBM);
    int fusedBlocks = (n * 32 + 255) / 256;

    // layer 1: 64 -> 4x64 concat, elu + LN (scores fused in GEMM epilogue)
    gemm_nt128<<<gq, 256>>>(x, W1, hbuf, n, 256, 64, a1s, a1d, sp, dp, 4);
    gat_fused<4><<<fusedBlocks, 256>>>(rowp, ecolp, sp, dp, hbuf, b1, ln1w, ln1b, xbuf, n, 1);

    // layer 2: 256 -> 4x64 concat, elu + LN
    gemm_nt128<<<gq, 256>>>(xbuf, W2, hbuf, n, 256, 256, a2s, a2d, sp, dp, 4);
    gat_fused<4><<<fusedBlocks, 256>>>(rowp, ecolp, sp, dp, hbuf, b2, ln2w, ln2b, xbuf, n, 1);

    // layer 3: 256 -> 1x64, LN only
    gemm_nt<<<g3, 256>>>(xbuf, W3, hbuf, n, 64, 256, a3s, a3d, sp, dp, 1);
    gat_fused<1><<<fusedBlocks, 256>>>(rowp, ecolp, sp, dp, hbuf, b3, ln3w, ln3b, ybuf, n, 0);

    // final MLP head
    size_t smem = (128 * 64 + 64 * 64 + 4 * 128 + 4 * 64) * sizeof(float);
    cudaFuncSetAttribute(head_kernel, cudaFuncAttributeMaxDynamicSharedMemorySize, (int)smem);
    head_kernel<<<(n + 63) / 64, 256, smem>>>(ybuf, rolep, rt, p1w, p1b, p2w, p2b, z, n);
}